// round 12
// baseline (speedup 1.0000x reference)
#include <cuda_runtime.h>
#include <math.h>
#include <stdint.h>

#define NMAXN 200000
#define EMAXE 400000
#define GMAXG 8192
#define CMAX  256
#define SCAN_NB 1024

// ---------------- scratch (static device globals; no allocation) ----------------
__device__ float g_bufA[(size_t)NMAXN * CMAX];
__device__ float g_bufB[(size_t)NMAXN * CMAX];
__device__ float g_dis[NMAXN];
__device__ float g_selfn[NMAXN];
__device__ int   g_degi[NMAXN];
__device__ int   g_rowStart[NMAXN + 1];
__device__ int   g_blkSum[SCAN_NB];
__device__ int   g_fill[NMAXN];
__device__ int   g_csr_src[EMAXE];
__device__ float g_csr_w[EMAXE];
__device__ float g_pooled[(size_t)GMAXG * CMAX];
__device__ float g_stats[3 * 512];     // per-layer slots: sum at [c], sumsq at [256+c]
__device__ float g_Wt2[128 * 256];
__device__ float g_Wt3[256 * 256];
__device__ float g_Wtp[256 * 256];

// ---------------- helpers ----------------
__device__ __forceinline__ uint32_t smem_u32(const void* p) {
    uint32_t a;
    asm("{ .reg .u64 t; cvta.to.shared.u64 t, %1; cvt.u32.u64 %0, t; }" : "=r"(a) : "l"(p));
    return a;
}
__device__ __forceinline__ float tf32r(float x) {
    uint32_t u;
    asm("cvt.rna.tf32.f32 %0, %1;" : "=r"(u) : "f"(x));
    return __uint_as_float(u);
}
__device__ __forceinline__ void mma_tf32(float d[4], const uint32_t a[4], const uint32_t b[2]) {
    asm volatile(
        "mma.sync.aligned.m16n8k8.row.col.f32.tf32.tf32.f32 "
        "{%0,%1,%2,%3}, {%4,%5,%6,%7}, {%8,%9}, {%0,%1,%2,%3};"
        : "+f"(d[0]), "+f"(d[1]), "+f"(d[2]), "+f"(d[3])
        : "r"(a[0]), "r"(a[1]), "r"(a[2]), "r"(a[3]), "r"(b[0]), "r"(b[1]));
}
__device__ __forceinline__ void cp_async8(uint32_t daddr, const void* gptr, uint32_t srcsz) {
    asm volatile("cp.async.ca.shared.global [%0], [%1], 8, %2;"
                 :: "r"(daddr), "l"(gptr), "r"(srcsz) : "memory");
}
#define CP_COMMIT() asm volatile("cp.async.commit_group;" ::: "memory")
#define CP_WAIT1()  asm volatile("cp.async.wait_group 1;" ::: "memory")

// BN coefficient from a stats slot (training-mode batch stats)
__device__ __forceinline__ void bn_coef(const float* stats, const float* gamma,
                                        const float* beta, int c, float invN,
                                        float& sc, float& sh) {
    float mean = stats[c] * invN;
    float var  = stats[256 + c] * invN - mean * mean;
    sc = gamma[c] * rsqrtf(var + 1e-5f);
    sh = beta[c] - mean * sc;
}

// ---------------- prep: zero counters/stats + tf32-transpose all weights ----------------
__global__ void k_zero_trans(const float* __restrict__ W2, const float* __restrict__ W3,
                             const float* __restrict__ Wp, int N) {
    int i = blockIdx.x * blockDim.x + threadIdx.x;
    if (i < N) { g_degi[i] = 0; g_fill[i] = 0; }
    if (i < 3 * 512) g_stats[i] = 0.f;
    if (i < 128 * 256) {
        int k = i / 256, n = i % 256;
        g_Wt2[(size_t)n * 128 + k] = tf32r(W2[i]);
    }
    if (i < 256 * 256) {
        int k = i / 256, n = i % 256;
        g_Wt3[(size_t)n * 256 + k] = tf32r(W3[i]);
        g_Wtp[(size_t)n * 256 + k] = tf32r(Wp[i]);
    }
}
__global__ void k_deg_accum(const int* __restrict__ dst, int E) {
    int e = blockIdx.x * blockDim.x + threadIdx.x;
    if (e < E) atomicAdd(&g_degi[dst[e]], 1);
}
__global__ void k_scan1(int N) {
    __shared__ int sh[256];
    int i = blockIdx.x * 256 + threadIdx.x;
    int v = (i < N) ? g_degi[i] : 0;
    if (i < N) {
        float d = (float)(v + 1);
        g_dis[i] = rsqrtf(d);
        g_selfn[i] = 1.0f / d;
    }
    sh[threadIdx.x] = v;
    __syncthreads();
    for (int off = 1; off < 256; off <<= 1) {
        int t = (threadIdx.x >= off) ? sh[threadIdx.x - off] : 0;
        __syncthreads();
        sh[threadIdx.x] += t;
        __syncthreads();
    }
    if (i < N) g_rowStart[i] = sh[threadIdx.x] - v;
    if (threadIdx.x == 255) g_blkSum[blockIdx.x] = sh[255];
}
__global__ void k_scan2(int NB) {
    __shared__ int sh[SCAN_NB];
    int v = ((int)threadIdx.x < NB) ? g_blkSum[threadIdx.x] : 0;
    sh[threadIdx.x] = v;
    __syncthreads();
    for (int off = 1; off < SCAN_NB; off <<= 1) {
        int t = ((int)threadIdx.x >= off) ? sh[threadIdx.x - off] : 0;
        __syncthreads();
        sh[threadIdx.x] += t;
        __syncthreads();
    }
    if ((int)threadIdx.x < NB) g_blkSum[threadIdx.x] = sh[threadIdx.x] - v;
}
__global__ void k_scan3(int N, int E) {
    int i = blockIdx.x * blockDim.x + threadIdx.x;
    if (i < N) g_rowStart[i] += g_blkSum[i >> 8];
    if (i == 0) g_rowStart[N] = E;
}
__global__ void k_csr_fill(const int* __restrict__ src, const int* __restrict__ dst, int E) {
    int e = blockIdx.x * blockDim.x + threadIdx.x;
    if (e < E) {
        int s = src[e], d = dst[e];
        int pos = g_rowStart[d] + atomicAdd(&g_fill[d], 1);
        g_csr_src[pos] = s;
        g_csr_w[pos]   = g_dis[s] * g_dis[d];
    }
}

// ---------------- fused layer-1: gather9 + GEMM[9->128] + stats (slot 0) ----------------
__global__ __launch_bounds__(256) void k_layer1(const float* __restrict__ x,
                                                const float* __restrict__ W1,
                                                float* __restrict__ Y, int N) {
    __shared__ float Ws[9 * 128];
    __shared__ float sstat[256];
    int tid = threadIdx.x;
    for (int i = tid; i < 9 * 128; i += 256) Ws[i] = W1[i];
    sstat[tid] = 0.f;
    __syncthreads();
    int wid = tid >> 5, lane = tid & 31;
    int i = blockIdx.x * 8 + wid;
    if (i < N) {
        float acc = 0.f;
        if (lane < 9) acc = g_selfn[i] * x[(size_t)i * 9 + lane];
        int st = g_rowStart[i], en = g_rowStart[i + 1];
        for (int j = st; j < en; j++) {
            int s = g_csr_src[j];
            float w = g_csr_w[j];
            if (lane < 9) acc += w * x[(size_t)s * 9 + lane];
        }
        float a[9];
#pragma unroll
        for (int k = 0; k < 9; k++) a[k] = __shfl_sync(0xFFFFFFFF, acc, k);
#pragma unroll
        for (int q = 0; q < 4; q++) {
            int c = q * 32 + lane;
            float y = 0.f;
#pragma unroll
            for (int k = 0; k < 9; k++) y += a[k] * Ws[k * 128 + c];
            Y[(size_t)i * 128 + c] = y;
            atomicAdd(&sstat[c], y);
            atomicAdd(&sstat[128 + c], y * y);
        }
    }
    __syncthreads();
    if (tid < 128) {
        atomicAdd(&g_stats[tid], sstat[tid]);
        atomicAdd(&g_stats[256 + tid], sstat[128 + tid]);
    }
}

// ---------------- gather + inline-BN+ReLU (stats slot -> coefficients computed in-thread) ----------------
// TPN = C/4 threads per node; NPB = 256/TPN nodes per block. (R7 configuration)
template <int C>
__global__ __launch_bounds__(256) void k_gather_bn4(const float* __restrict__ Y,
                                                    float* __restrict__ P, int N,
                                                    const float* __restrict__ stats,
                                                    const float* __restrict__ gamma,
                                                    const float* __restrict__ beta,
                                                    float invN) {
    constexpr int TPN = C / 4;
    constexpr int NPB = 256 / TPN;
    const int sub = threadIdx.x / TPN;
    const int cq  = threadIdx.x % TPN;
    const int i   = blockIdx.x * NPB + sub;
    if (i >= N) return;
    float4 sc, sh;
    bn_coef(stats, gamma, beta, cq * 4 + 0, invN, sc.x, sh.x);
    bn_coef(stats, gamma, beta, cq * 4 + 1, invN, sc.y, sh.y);
    bn_coef(stats, gamma, beta, cq * 4 + 2, invN, sc.z, sh.z);
    bn_coef(stats, gamma, beta, cq * 4 + 3, invN, sc.w, sh.w);
    const float4* Yv = (const float4*)Y;
    float w0 = g_selfn[i];
    float4 y = Yv[(size_t)i * TPN + cq];
    float4 acc;
    acc.x = w0 * fmaxf(0.f, y.x * sc.x + sh.x);
    acc.y = w0 * fmaxf(0.f, y.y * sc.y + sh.y);
    acc.z = w0 * fmaxf(0.f, y.z * sc.z + sh.z);
    acc.w = w0 * fmaxf(0.f, y.w * sc.w + sh.w);
    int st = g_rowStart[i], en = g_rowStart[i + 1];
    for (int j = st; j < en; j++) {
        int s = g_csr_src[j];
        float w = g_csr_w[j];
        float4 v = Yv[(size_t)s * TPN + cq];
        acc.x += w * fmaxf(0.f, v.x * sc.x + sh.x);
        acc.y += w * fmaxf(0.f, v.y * sc.y + sh.y);
        acc.z += w * fmaxf(0.f, v.z * sc.z + sh.z);
        acc.w += w * fmaxf(0.f, v.w * sc.w + sh.w);
    }
    ((float4*)P)[(size_t)i * TPN + cq] =
        make_float4(tf32r(acc.x), tf32r(acc.y), tf32r(acc.z), tf32r(acc.w));
}

// ---------------- tf32 mma GEMM, cp.async double-buffered, fused stats ----------------
__global__ __launch_bounds__(256, 2) void k_mma(const float* __restrict__ A,
                                                const float* __restrict__ Wt,
                                                float* __restrict__ C,
                                                int M, int K,
                                                const float* __restrict__ bias,
                                                float* __restrict__ statsOut) {
    extern __shared__ __align__(16) float sm[];
    const int tid  = threadIdx.x;
    const int wid  = tid >> 5;
    const int lane = tid & 31;
    const int wr   = (wid & 1) * 64;
    const int wc   = (wid >> 1) * 32;
    const int row0 = blockIdx.y * 128;
    const int col0 = blockIdx.x * 128;
    const int gq   = lane >> 2;
    const int tq   = lane & 3;
    const uint32_t sbase = smem_u32(sm);
    const int nk = K >> 5;

    float acc[4][4][4];
#pragma unroll
    for (int mt = 0; mt < 4; mt++)
#pragma unroll
        for (int nt = 0; nt < 4; nt++)
#pragma unroll
            for (int q = 0; q < 4; q++) acc[mt][nt][q] = 0.f;

    auto load_stage = [&](int s, int k0) {
#pragma unroll
        for (int i = 0; i < 8; i++) {
            int idx = tid + i * 256;
            int r = idx >> 4, j2 = idx & 15;
            int gr = row0 + r;
            uint32_t da = sbase + (uint32_t)(s * 4608 + r * 36 + j2 * 2) * 4;
            cp_async8(da, A + (size_t)gr * K + k0 + j2 * 2, (gr < M) ? 8u : 0u);
        }
#pragma unroll
        for (int i = 0; i < 8; i++) {
            int idx = tid + i * 256;
            int n = idx >> 4, j2 = idx & 15;
            uint32_t db = sbase + (uint32_t)(9216 + s * 4608 + n * 36 + j2 * 2) * 4;
            cp_async8(db, Wt + (size_t)(col0 + n) * K + k0 + j2 * 2, 8u);
        }
    };

    load_stage(0, 0);
    CP_COMMIT();
    for (int kt = 0; kt < nk; kt++) {
        if (kt + 1 < nk) load_stage((kt + 1) & 1, (kt + 1) * 32);
        CP_COMMIT();
        CP_WAIT1();
        __syncthreads();
        const float* As = sm + (kt & 1) * 4608;
        const float* Bs = sm + 9216 + (kt & 1) * 4608;
#pragma unroll
        for (int kk = 0; kk < 4; kk++) {
            uint32_t af[4][4], bf[4][2];
#pragma unroll
            for (int mt = 0; mt < 4; mt++) {
                int r = wr + mt * 16 + gq;
                af[mt][0] = __float_as_uint(As[r * 36 + kk * 8 + tq]);
                af[mt][1] = __float_as_uint(As[(r + 8) * 36 + kk * 8 + tq]);
                af[mt][2] = __float_as_uint(As[r * 36 + kk * 8 + 4 + tq]);
                af[mt][3] = __float_as_uint(As[(r + 8) * 36 + kk * 8 + 4 + tq]);
            }
#pragma unroll
            for (int nt = 0; nt < 4; nt++) {
                int n = wc + nt * 8 + gq;
                bf[nt][0] = __float_as_uint(Bs[n * 36 + kk * 8 + tq]);
                bf[nt][1] = __float_as_uint(Bs[n * 36 + kk * 8 + 4 + tq]);
            }
#pragma unroll
            for (int mt = 0; mt < 4; mt++)
#pragma unroll
                for (int nt = 0; nt < 4; nt++)
                    mma_tf32(acc[mt][nt], af[mt], bf[nt]);
        }
        __syncthreads();
    }

#pragma unroll
    for (int mt = 0; mt < 4; mt++) {
        int r0 = row0 + wr + mt * 16 + gq;
        int r1 = r0 + 8;
#pragma unroll
        for (int nt = 0; nt < 4; nt++) {
            int c = col0 + wc + nt * 8 + tq * 2;
            float b0 = 0.f, b1 = 0.f;
            if (bias) { b0 = bias[c]; b1 = bias[c + 1]; }
            if (r0 < M)
                *(float2*)(C + (size_t)r0 * 256 + c) =
                    make_float2(acc[mt][nt][0] + b0, acc[mt][nt][1] + b1);
            if (r1 < M)
                *(float2*)(C + (size_t)r1 * 256 + c) =
                    make_float2(acc[mt][nt][2] + b0, acc[mt][nt][3] + b1);
        }
    }

    if (statsOut) {
#pragma unroll
        for (int nt = 0; nt < 4; nt++) {
#pragma unroll
            for (int q = 0; q < 2; q++) {
                float s = 0.f, sq = 0.f;
#pragma unroll
                for (int mt = 0; mt < 4; mt++) {
                    float a = acc[mt][nt][q], b = acc[mt][nt][q + 2];
                    s += a + b;
                    sq += a * a + b * b;
                }
#pragma unroll
                for (int off = 4; off < 32; off <<= 1) {
                    s  += __shfl_xor_sync(0xFFFFFFFF, s, off);
                    sq += __shfl_xor_sync(0xFFFFFFFF, sq, off);
                }
                if (gq == 0) {
                    int c = col0 + wc + nt * 8 + tq * 2 + q;
                    atomicAdd(&statsOut[c], s);
                    atomicAdd(&statsOut[256 + c], sq);
                }
            }
        }
    }
}

// ---------------- pool with inline BN+ReLU (batch sorted) ----------------
__global__ void k_pool(const float* __restrict__ Y, const int* __restrict__ batch,
                       int N, int G,
                       const float* __restrict__ stats,
                       const float* __restrict__ gamma,
                       const float* __restrict__ beta, float invN) {
    int g = blockIdx.x;
    int c = threadIdx.x;
    __shared__ int s_lo, s_hi;
    if (c == 0) {
        int lo = 0, hi = N;
        while (lo < hi) { int m = (lo + hi) >> 1; if (batch[m] < g) lo = m + 1; else hi = m; }
        s_lo = lo;
        int lo2 = lo, hi2 = N;
        while (lo2 < hi2) { int m = (lo2 + hi2) >> 1; if (batch[m] <= g) lo2 = m + 1; else hi2 = m; }
        s_hi = lo2;
    }
    float sc, sh;
    bn_coef(stats, gamma, beta, c, invN, sc, sh);
    __syncthreads();
    float sum = 0.f;
    for (int i = s_lo; i < s_hi; i++)
        sum += fmaxf(0.f, Y[(size_t)i * 256 + c] * sc + sh);
    int cnt = s_hi - s_lo;
    g_pooled[(size_t)g * 256 + c] = tf32r(sum / fmaxf((float)cnt, 1.0f));
}

// ---------------- host launcher ----------------
extern "C" void kernel_launch(void* const* d_in, const int* in_sizes, int n_in,
                              void* d_out, int out_size) {
    const float* x     = (const float*)d_in[0];
    const int*   ei    = (const int*)d_in[1];
    const int*   batch = (const int*)d_in[2];
    const float* W1  = (const float*)d_in[4];
    const float* g1  = (const float*)d_in[6];
    const float* be1 = (const float*)d_in[7];
    const float* W2  = (const float*)d_in[8];
    const float* g2  = (const float*)d_in[10];
    const float* be2 = (const float*)d_in[11];
    const float* W3  = (const float*)d_in[12];
    const float* g3  = (const float*)d_in[14];
    const float* be3 = (const float*)d_in[15];
    const float* Wp  = (const float*)d_in[16];
    const float* bp  = (const float*)d_in[17];
    float* out = (float*)d_out;

    const int N = in_sizes[0] / 9;
    const int E = in_sizes[1] / 2;
    const int G = out_size / 256;
    const int NB = (N + 255) / 256;
    const int SMEM_MMA = 4 * 4608 * 4;
    const float invN = 1.0f / (float)N;

    cudaFuncSetAttribute(k_mma, cudaFuncAttributeMaxDynamicSharedMemorySize, SMEM_MMA);

    void *pA, *pB, *pPooled, *pWt2, *pWt3, *pWtp, *pStats;
    cudaGetSymbolAddress(&pA, g_bufA);
    cudaGetSymbolAddress(&pB, g_bufB);
    cudaGetSymbolAddress(&pPooled, g_pooled);
    cudaGetSymbolAddress(&pWt2, g_Wt2);
    cudaGetSymbolAddress(&pWt3, g_Wt3);
    cudaGetSymbolAddress(&pWtp, g_Wtp);
    cudaGetSymbolAddress(&pStats, g_stats);
    float* bufA = (float*)pA;
    float* bufB = (float*)pB;
    float* stats0 = (float*)pStats;
    float* stats1 = stats0 + 512;
    float* stats2 = stats0 + 1024;

    const int* src = ei;
    const int* dst = ei + E;

    // ---- prep ----
    k_zero_trans<<<NB, 256>>>(W2, W3, Wp, N);
    k_deg_accum<<<(E + 255) / 256, 256>>>(dst, E);
    k_scan1<<<NB, 256>>>(N);
    k_scan2<<<1, SCAN_NB>>>(NB);
    k_scan3<<<NB, 256>>>(N, E);
    k_csr_fill<<<(E + 255) / 256, 256>>>(src, dst, E);

    // ---- Layer 1 (fused gather + GEMM + stats slot0) ----
    k_layer1<<<(N + 7) / 8, 256>>>(x, W1, bufB, N);

    // ---- Layer 2 ----
    k_gather_bn4<128><<<(N + 7) / 8, 256>>>(bufB, bufA, N, stats0, g1, be1, invN);
    {
        dim3 grid(2, (N + 127) / 128);
        k_mma<<<grid, 256, SMEM_MMA>>>(bufA, (const float*)pWt2, bufB, N, 128, nullptr, stats1);
    }

    // ---- Layer 3 ----
    k_gather_bn4<256><<<(N + 3) / 4, 256>>>(bufB, bufA, N, stats1, g2, be2, invN);
    {
        dim3 grid(2, (N + 127) / 128);
        k_mma<<<grid, 256, SMEM_MMA>>>(bufA, (const float*)pWt3, bufB, N, 256, nullptr, stats2);
    }

    // ---- pool (inline BN3+ReLU) + final linear ----
    k_pool<<<G, 256>>>(bufB, batch, N, G, stats2, g3, be3, invN);
    {
        dim3 grid(2, (G + 127) / 128);
        k_mma<<<grid, 256, SMEM_MMA>>>((const float*)pPooled, (const float*)pWtp, out,
                                       G, 256, bp, nullptr);
    }
}

// round 15
// speedup vs baseline: 1.2516x; 1.2516x over previous
#include <cuda_runtime.h>
#include <cuda_fp16.h>
#include <math.h>
#include <stdint.h>

#define NMAXN 200000
#define EMAXE 400000
#define GMAXG 8192
#define CMAX  256
#define SCAN_NB 1024

// ---------------- scratch (static device globals; no allocation) ----------------
__device__ float  g_bufA[(size_t)NMAXN * CMAX];   // P (as half, reinterpreted) 
__device__ float  g_bufB[(size_t)NMAXN * CMAX];   // Y (fp32 GEMM outputs)
__device__ float  g_dis[NMAXN];
__device__ float  g_selfn[NMAXN];
__device__ int    g_degi[NMAXN];
__device__ int    g_rowStart[NMAXN + 1];
__device__ int    g_blkSum[SCAN_NB];
__device__ int    g_fill[NMAXN];
__device__ int    g_csr_src[EMAXE];
__device__ float  g_csr_w[EMAXE];
__device__ __half g_pooledh[(size_t)GMAXG * CMAX];
__device__ float  g_stats[2 * CMAX];
__device__ float  g_scale[CMAX];
__device__ float  g_shift[CMAX];
__device__ __half g_Wt2h[128 * 256];
__device__ __half g_Wt3h[256 * 256];
__device__ __half g_Wtph[256 * 256];

// ---------------- helpers ----------------
__device__ __forceinline__ uint32_t smem_u32(const void* p) {
    uint32_t a;
    asm("{ .reg .u64 t; cvta.to.shared.u64 t, %1; cvt.u32.u64 %0, t; }" : "=r"(a) : "l"(p));
    return a;
}
__device__ __forceinline__ void mma_f16(float d[4], uint32_t a0, uint32_t a1,
                                        uint32_t a2, uint32_t a3,
                                        uint32_t b0, uint32_t b1) {
    asm volatile(
        "mma.sync.aligned.m16n8k16.row.col.f32.f16.f16.f32 "
        "{%0,%1,%2,%3}, {%4,%5,%6,%7}, {%8,%9}, {%0,%1,%2,%3};"
        : "+f"(d[0]), "+f"(d[1]), "+f"(d[2]), "+f"(d[3])
        : "r"(a0), "r"(a1), "r"(a2), "r"(a3), "r"(b0), "r"(b1));
}
__device__ __forceinline__ void cp_async16(uint32_t daddr, const void* gptr, uint32_t srcsz) {
    asm volatile("cp.async.ca.shared.global [%0], [%1], 16, %2;"
                 :: "r"(daddr), "l"(gptr), "r"(srcsz) : "memory");
}
#define CP_COMMIT() asm volatile("cp.async.commit_group;" ::: "memory")
#define CP_WAIT1()  asm volatile("cp.async.wait_group 1;" ::: "memory")

// ---------------- prep: zero counters + fp16-transpose all weights ----------------
__global__ void k_zero_trans(const float* __restrict__ W2, const float* __restrict__ W3,
                             const float* __restrict__ Wp, int N) {
    int i = blockIdx.x * blockDim.x + threadIdx.x;
    if (i < N) { g_degi[i] = 0; g_fill[i] = 0; }
    if (i < 2 * CMAX) g_stats[i] = 0.f;
    if (i < 128 * 256) {
        int k = i / 256, n = i % 256;
        g_Wt2h[(size_t)n * 128 + k] = __float2half_rn(W2[i]);
    }
    if (i < 256 * 256) {
        int k = i / 256, n = i % 256;
        g_Wt3h[(size_t)n * 256 + k] = __float2half_rn(W3[i]);
        g_Wtph[(size_t)n * 256 + k] = __float2half_rn(Wp[i]);
    }
}
__global__ void k_deg_accum(const int* __restrict__ dst, int E) {
    int e = blockIdx.x * blockDim.x + threadIdx.x;
    if (e < E) atomicAdd(&g_degi[dst[e]], 1);
}
__global__ void k_scan1(int N) {
    __shared__ int sh[256];
    int i = blockIdx.x * 256 + threadIdx.x;
    int v = (i < N) ? g_degi[i] : 0;
    if (i < N) {
        float d = (float)(v + 1);
        g_dis[i] = rsqrtf(d);
        g_selfn[i] = 1.0f / d;
    }
    sh[threadIdx.x] = v;
    __syncthreads();
    for (int off = 1; off < 256; off <<= 1) {
        int t = (threadIdx.x >= off) ? sh[threadIdx.x - off] : 0;
        __syncthreads();
        sh[threadIdx.x] += t;
        __syncthreads();
    }
    if (i < N) g_rowStart[i] = sh[threadIdx.x] - v;
    if (threadIdx.x == 255) g_blkSum[blockIdx.x] = sh[255];
}
__global__ void k_scan2(int NB) {
    __shared__ int sh[SCAN_NB];
    int v = ((int)threadIdx.x < NB) ? g_blkSum[threadIdx.x] : 0;
    sh[threadIdx.x] = v;
    __syncthreads();
    for (int off = 1; off < SCAN_NB; off <<= 1) {
        int t = ((int)threadIdx.x >= off) ? sh[threadIdx.x - off] : 0;
        __syncthreads();
        sh[threadIdx.x] += t;
        __syncthreads();
    }
    if ((int)threadIdx.x < NB) g_blkSum[threadIdx.x] = sh[threadIdx.x] - v;
}
__global__ void k_scan3(int N, int E) {
    int i = blockIdx.x * blockDim.x + threadIdx.x;
    if (i < N) g_rowStart[i] += g_blkSum[i >> 8];
    if (i == 0) g_rowStart[N] = E;
}
__global__ void k_csr_fill(const int* __restrict__ src, const int* __restrict__ dst, int E) {
    int e = blockIdx.x * blockDim.x + threadIdx.x;
    if (e < E) {
        int s = src[e], d = dst[e];
        int pos = g_rowStart[d] + atomicAdd(&g_fill[d], 1);
        g_csr_src[pos] = s;
        g_csr_w[pos]   = g_dis[s] * g_dis[d];
    }
}

// ---------------- fused layer-1: gather9 + GEMM[9->128] + stats ----------------
__global__ __launch_bounds__(256) void k_layer1(const float* __restrict__ x,
                                                const float* __restrict__ W1,
                                                float* __restrict__ Y, int N) {
    __shared__ float Ws[9 * 128];
    __shared__ float sstat[256];
    int tid = threadIdx.x;
    for (int i = tid; i < 9 * 128; i += 256) Ws[i] = W1[i];
    sstat[tid] = 0.f;
    __syncthreads();
    int wid = tid >> 5, lane = tid & 31;
    int i = blockIdx.x * 8 + wid;
    if (i < N) {
        float acc = 0.f;
        if (lane < 9) acc = g_selfn[i] * x[(size_t)i * 9 + lane];
        int st = g_rowStart[i], en = g_rowStart[i + 1];
        for (int j = st; j < en; j++) {
            int s = g_csr_src[j];
            float w = g_csr_w[j];
            if (lane < 9) acc += w * x[(size_t)s * 9 + lane];
        }
        float a[9];
#pragma unroll
        for (int k = 0; k < 9; k++) a[k] = __shfl_sync(0xFFFFFFFF, acc, k);
#pragma unroll
        for (int q = 0; q < 4; q++) {
            int c = q * 32 + lane;
            float y = 0.f;
#pragma unroll
            for (int k = 0; k < 9; k++) y += a[k] * Ws[k * 128 + c];
            Y[(size_t)i * 128 + c] = y;
            atomicAdd(&sstat[c], y);
            atomicAdd(&sstat[128 + c], y * y);
        }
    }
    __syncthreads();
    if (tid < 128) {
        atomicAdd(&g_stats[tid], sstat[tid]);
        atomicAdd(&g_stats[256 + tid], sstat[128 + tid]);
    }
}

// ---------------- BN finalize (resets stats for next layer) ----------------
__global__ void k_finalize(const float* __restrict__ gamma,
                           const float* __restrict__ beta, int N, int C) {
    int c = threadIdx.x;
    if (c < C) {
        float invN = 1.0f / (float)N;
        float mean = g_stats[c] * invN;
        float var  = g_stats[256 + c] * invN - mean * mean;
        float sc   = gamma[c] * rsqrtf(var + 1e-5f);
        g_scale[c] = sc;
        g_shift[c] = beta[c] - mean * sc;
        g_stats[c] = 0.f;
        g_stats[256 + c] = 0.f;
    }
}

// ---------------- gather + fused BN+ReLU (R7 config), fp16 output ----------------
// TPN = C/4 threads per node; NPB = 256/TPN nodes per block.
template <int C>
__global__ __launch_bounds__(256) void k_gather_bn4(const float* __restrict__ Y,
                                                    __half* __restrict__ P, int N) {
    constexpr int TPN = C / 4;
    constexpr int NPB = 256 / TPN;
    const int sub = threadIdx.x / TPN;
    const int cq  = threadIdx.x % TPN;
    const int i   = blockIdx.x * NPB + sub;
    if (i >= N) return;
    const float4 sc = ((const float4*)g_scale)[cq];
    const float4 sh = ((const float4*)g_shift)[cq];
    const float4* Yv = (const float4*)Y;
    float w0 = g_selfn[i];
    float4 y = Yv[(size_t)i * TPN + cq];
    float4 acc;
    acc.x = w0 * fmaxf(0.f, y.x * sc.x + sh.x);
    acc.y = w0 * fmaxf(0.f, y.y * sc.y + sh.y);
    acc.z = w0 * fmaxf(0.f, y.z * sc.z + sh.z);
    acc.w = w0 * fmaxf(0.f, y.w * sc.w + sh.w);
    int st = g_rowStart[i], en = g_rowStart[i + 1];
    for (int j = st; j < en; j++) {
        int s = g_csr_src[j];
        float w = g_csr_w[j];
        float4 v = Yv[(size_t)s * TPN + cq];
        acc.x += w * fmaxf(0.f, v.x * sc.x + sh.x);
        acc.y += w * fmaxf(0.f, v.y * sc.y + sh.y);
        acc.z += w * fmaxf(0.f, v.z * sc.z + sh.z);
        acc.w += w * fmaxf(0.f, v.w * sc.w + sh.w);
    }
    __half2 h0 = __floats2half2_rn(acc.x, acc.y);
    __half2 h1 = __floats2half2_rn(acc.z, acc.w);
    uint2 pk;
    pk.x = *(uint32_t*)&h0;
    pk.y = *(uint32_t*)&h1;
    *(uint2*)(P + (size_t)i * C + cq * 4) = pk;
}

// ---------------- fp16 mma GEMM (m16n8k16), cp.async double-buffered, fused stats ----------------
// C[M,256] = A[M,K](half) @ Wt^T (Wt [256,K] half). 128x128 tile, 256 thr, occ 2.
// smem rows: 32 halves data + 8 pad = 40 halves (80 B stride).
__global__ __launch_bounds__(256, 2) void k_mma_h(const __half* __restrict__ A,
                                                  const __half* __restrict__ Wt,
                                                  float* __restrict__ C,
                                                  int M, int K,
                                                  const float* __restrict__ bias,
                                                  int doStats) {
    extern __shared__ __align__(16) char smc[];
    const int tid  = threadIdx.x;
    const int wid  = tid >> 5;
    const int lane = tid & 31;
    const int wr   = (wid & 1) * 64;
    const int wc   = (wid >> 1) * 32;
    const int row0 = blockIdx.y * 128;
    const int col0 = blockIdx.x * 128;
    const int gq   = lane >> 2;
    const int tq   = lane & 3;
    const uint32_t sbase = smem_u32(smc);
    const int nk = K >> 5;
    // byte layout: A stage s at s*10240, B stage s at 20480 + s*10240 (each 128 rows * 80 B)

    float acc[4][4][4];
#pragma unroll
    for (int mt = 0; mt < 4; mt++)
#pragma unroll
        for (int nt = 0; nt < 4; nt++)
#pragma unroll
            for (int q = 0; q < 4; q++) acc[mt][nt][q] = 0.f;

    auto load_stage = [&](int s, int k0) {
#pragma unroll
        for (int i = 0; i < 2; i++) {
            int idx = tid + i * 256;           // 0..511
            int r = idx >> 2, j = idx & 3;     // row, 16B chunk (8 halves)
            int gr = row0 + r;
            uint32_t da = sbase + (uint32_t)(s * 10240 + r * 80 + j * 16);
            cp_async16(da, A + (size_t)gr * K + k0 + j * 8, (gr < M) ? 16u : 0u);
        }
#pragma unroll
        for (int i = 0; i < 2; i++) {
            int idx = tid + i * 256;
            int n = idx >> 2, j = idx & 3;
            uint32_t db = sbase + (uint32_t)(20480 + s * 10240 + n * 80 + j * 16);
            cp_async16(db, Wt + (size_t)(col0 + n) * K + k0 + j * 8, 16u);
        }
    };

    load_stage(0, 0);
    CP_COMMIT();
    for (int kt = 0; kt < nk; kt++) {
        if (kt + 1 < nk) load_stage((kt + 1) & 1, (kt + 1) * 32);
        CP_COMMIT();
        CP_WAIT1();
        __syncthreads();
        const char* As = smc + (kt & 1) * 10240;
        const char* Bs = smc + 20480 + (kt & 1) * 10240;
#pragma unroll
        for (int kk = 0; kk < 2; kk++) {      // two k16 steps per 32-k tile
            const int cb = kk * 32 + tq * 4;  // byte col offset (kk*16 halves, tq*2 halves)
            uint32_t af[4][4], bf[4][2];
#pragma unroll
            for (int mt = 0; mt < 4; mt++) {
                int r = wr + mt * 16 + gq;
                const char* p0 = As + r * 80 + cb;
                af[mt][0] = *(const uint32_t*)(p0);            // row r,   k +0,1
                af[mt][1] = *(const uint32_t*)(p0 + 8 * 80);   // row r+8, k +0,1
                af[mt][2] = *(const uint32_t*)(p0 + 16);       // row r,   k +8,9
                af[mt][3] = *(const uint32_t*)(p0 + 8 * 80 + 16);
            }
#pragma unroll
            for (int nt = 0; nt < 4; nt++) {
                int n = wc + nt * 8 + gq;
                const char* p0 = Bs + n * 80 + cb;
                bf[nt][0] = *(const uint32_t*)(p0);
                bf[nt][1] = *(const uint32_t*)(p0 + 16);
            }
#pragma unroll
            for (int mt = 0; mt < 4; mt++)
#pragma unroll
                for (int nt = 0; nt < 4; nt++)
                    mma_f16(acc[mt][nt], af[mt][0], af[mt][1], af[mt][2], af[mt][3],
                            bf[nt][0], bf[nt][1]);
        }
        __syncthreads();
    }

#pragma unroll
    for (int mt = 0; mt < 4; mt++) {
        int r0 = row0 + wr + mt * 16 + gq;
        int r1 = r0 + 8;
#pragma unroll
        for (int nt = 0; nt < 4; nt++) {
            int c = col0 + wc + nt * 8 + tq * 2;
            float b0 = 0.f, b1 = 0.f;
            if (bias) { b0 = bias[c]; b1 = bias[c + 1]; }
            if (r0 < M)
                *(float2*)(C + (size_t)r0 * 256 + c) =
                    make_float2(acc[mt][nt][0] + b0, acc[mt][nt][1] + b1);
            if (r1 < M)
                *(float2*)(C + (size_t)r1 * 256 + c) =
                    make_float2(acc[mt][nt][2] + b0, acc[mt][nt][3] + b1);
        }
    }

    if (doStats) {
#pragma unroll
        for (int nt = 0; nt < 4; nt++) {
#pragma unroll
            for (int q = 0; q < 2; q++) {
                float s = 0.f, sq = 0.f;
#pragma unroll
                for (int mt = 0; mt < 4; mt++) {
                    float a = acc[mt][nt][q], b = acc[mt][nt][q + 2];
                    s += a + b;
                    sq += a * a + b * b;
                }
#pragma unroll
                for (int off = 4; off < 32; off <<= 1) {
                    s  += __shfl_xor_sync(0xFFFFFFFF, s, off);
                    sq += __shfl_xor_sync(0xFFFFFFFF, sq, off);
                }
                if (gq == 0) {
                    int c = col0 + wc + nt * 8 + tq * 2 + q;
                    atomicAdd(&g_stats[c], s);
                    atomicAdd(&g_stats[256 + c], sq);
                }
            }
        }
    }
}

// ---------------- pool with fused BN+ReLU (batch sorted), fp16 output ----------------
__global__ void k_pool(const float* __restrict__ Y, const int* __restrict__ batch,
                       int N, int G) {
    int g = blockIdx.x;
    int c = threadIdx.x;
    __shared__ int s_lo, s_hi;
    if (c == 0) {
        int lo = 0, hi = N;
        while (lo < hi) { int m = (lo + hi) >> 1; if (batch[m] < g) lo = m + 1; else hi = m; }
        s_lo = lo;
        int lo2 = lo, hi2 = N;
        while (lo2 < hi2) { int m = (lo2 + hi2) >> 1; if (batch[m] <= g) lo2 = m + 1; else hi2 = m; }
        s_hi = lo2;
    }
    __syncthreads();
    float sc = g_scale[c], sh = g_shift[c];
    float sum = 0.f;
    for (int i = s_lo; i < s_hi; i++)
        sum += fmaxf(0.f, Y[(size_t)i * 256 + c] * sc + sh);
    int cnt = s_hi - s_lo;
    g_pooledh[(size_t)g * 256 + c] = __float2half_rn(sum / fmaxf((float)cnt, 1.0f));
}

// ---------------- host launcher ----------------
extern "C" void kernel_launch(void* const* d_in, const int* in_sizes, int n_in,
                              void* d_out, int out_size) {
    const float* x     = (const float*)d_in[0];
    const int*   ei    = (const int*)d_in[1];
    const int*   batch = (const int*)d_in[2];
    const float* W1  = (const float*)d_in[4];
    const float* g1  = (const float*)d_in[6];
    const float* be1 = (const float*)d_in[7];
    const float* W2  = (const float*)d_in[8];
    const float* g2  = (const float*)d_in[10];
    const float* be2 = (const float*)d_in[11];
    const float* W3  = (const float*)d_in[12];
    const float* g3  = (const float*)d_in[14];
    const float* be3 = (const float*)d_in[15];
    const float* Wp  = (const float*)d_in[16];
    const float* bp  = (const float*)d_in[17];
    float* out = (float*)d_out;

    const int N = in_sizes[0] / 9;
    const int E = in_sizes[1] / 2;
    const int G = out_size / 256;
    const int NB = (N + 255) / 256;
    const int SMEM_MMA = 4 * 10240;   // 40 KB -> occupancy 2

    cudaFuncSetAttribute(k_mma_h, cudaFuncAttributeMaxDynamicSharedMemorySize, SMEM_MMA);

    void *pA, *pB, *pPooled, *pWt2, *pWt3, *pWtp;
    cudaGetSymbolAddress(&pA, g_bufA);
    cudaGetSymbolAddress(&pB, g_bufB);
    cudaGetSymbolAddress(&pPooled, g_pooledh);
    cudaGetSymbolAddress(&pWt2, g_Wt2h);
    cudaGetSymbolAddress(&pWt3, g_Wt3h);
    cudaGetSymbolAddress(&pWtp, g_Wtph);
    __half* Ph   = (__half*)pA;     // fp16 gather outputs
    float*  bufB = (float*)pB;      // fp32 GEMM outputs

    const int* src = ei;
    const int* dst = ei + E;

    // ---- prep ----
    k_zero_trans<<<NB, 256>>>(W2, W3, Wp, N);
    k_deg_accum<<<(E + 255) / 256, 256>>>(dst, E);
    k_scan1<<<NB, 256>>>(N);
    k_scan2<<<1, SCAN_NB>>>(NB);
    k_scan3<<<NB, 256>>>(N, E);
    k_csr_fill<<<(E + 255) / 256, 256>>>(src, dst, E);

    // ---- Layer 1: gather9 + GEMM + stats -> Y1 (fp32) in bufB ----
    k_layer1<<<(N + 7) / 8, 256>>>(x, W1, bufB, N);
    k_finalize<<<1, 128>>>(g1, be1, N, 128);

    // ---- Layer 2: gather(Y1)->P(half); P @ W2 -> Y2 (fp32) in bufB ----
    k_gather_bn4<128><<<(N + 7) / 8, 256>>>(bufB, Ph, N);
    {
        dim3 grid(2, (N + 127) / 128);
        k_mma_h<<<grid, 256, SMEM_MMA>>>(Ph, (const __half*)pWt2, bufB, N, 128, nullptr, 1);
    }
    k_finalize<<<1, 256>>>(g2, be2, N, 256);

    // ---- Layer 3: gather(Y2)->P(half); P @ W3 -> Y3 (fp32) in bufB ----
    k_gather_bn4<256><<<(N + 3) / 4, 256>>>(bufB, Ph, N);
    {
        dim3 grid(2, (N + 127) / 128);
        k_mma_h<<<grid, 256, SMEM_MMA>>>(Ph, (const __half*)pWt3, bufB, N, 256, nullptr, 1);
    }
    k_finalize<<<1, 256>>>(g3, be3, N, 256);

    // ---- pool (fused BN3+ReLU, fp16 out) + final linear ----
    k_pool<<<G, 256>>>(bufB, batch, N, G);
    {
        dim3 grid(2, (G + 127) / 128);
        k_mma_h<<<grid, 256, SMEM_MMA>>>((const __half*)pPooled, (const __half*)pWtp, out,
                                         G, 256, bp, 0);
    }
}